// round 11
// baseline (speedup 1.0000x reference)
#include <cuda_runtime.h>
#include <cuda_bf16.h>
#include <math.h>
#include <stdint.h>

#define NN 40
#define BB 32
#define DD 768
#define TT 820
#define MAXM 49920   // outside L=1: 40*39*32 combos

typedef __nv_bfloat16 bf16;
typedef __nv_bfloat162 bf162;

// ---------------- static scratch (no allocations allowed) ----------------
__device__ float g_iv [(size_t)TT * BB * DD];        // inside vectors (fp32)
__device__ float g_ov [(size_t)TT * BB * DD];        // outside vectors (fp32)
__device__ float g_isc[TT * BB];                     // inside scores
__device__ float g_osc[TT * BB];                     // outside scores
__device__ float g_P  [(size_t)TT * BB * 3 * DD];    // [Pl | Pr | R] per cell/batch (fp32)
__device__ float g_Po [(size_t)TT * BB * DD];        // ov @ W1a^T (fp32)
__device__ bf16  g_Hb [(size_t)MAXM * DD];           // hidden scratch (bf16)
__device__ float g_V  [(size_t)MAXM * DD];           // compose output scratch
__device__ float g_S  [MAXM];                        // scores scratch
__device__ bf16  g_Wcatb[3 * DD * DD];               // bf16 rows: W1a | W1b | W_bil
__device__ bf16  g_W2b  [DD * DD];                   // bf16 W2

__host__ __device__ __forceinline__ int offL(int L) {
    return TT - (42 - L) * (41 - L) / 2;   // first chart index of spans of length L
}

__device__ __forceinline__ float blockReduce256(float v) {
    __shared__ float sh[8];
    int lane = threadIdx.x & 31, w = threadIdx.x >> 5;
    #pragma unroll
    for (int o = 16; o; o >>= 1) v += __shfl_down_sync(0xffffffffu, v, o);
    __syncthreads();
    if (lane == 0) sh[w] = v;
    __syncthreads();
    if (threadIdx.x == 0) {
        float s = 0.f;
        #pragma unroll
        for (int i = 0; i < 8; i++) s += sh[i];
        v = s;
    }
    __syncthreads();
    return v;
}

// ---------------- merged init kernel ----------------
#define R0 (TT * BB)                 // isc/osc zero
#define R1 (NN * BB * DD)            // copy base -> iv
#define R2 (BB * DD)                 // root bias -> ov[root]
#define R3 (3 * DD * DD)             // Wcat build (bf16)
#define R4 (DD * DD)                 // W2 convert (bf16)
__global__ void k_init(const float* __restrict__ base, const float* __restrict__ rb,
                       const float* __restrict__ W1, const float* __restrict__ Wb,
                       const float* __restrict__ W2) {
    long long i = (long long)blockIdx.x * 256 + threadIdx.x;
    if (i < R0) { g_isc[i] = 0.f; g_osc[i] = 0.f; return; }
    i -= R0;
    if (i < R1) { g_iv[i] = base[i]; return; }
    i -= R1;
    if (i < R2) { g_ov[(size_t)offL(NN) * BB * DD + i] = rb[i % DD]; return; }
    i -= R2;
    if (i < R3) {
        int j = (int)(i / DD), k = (int)(i % DD);
        float v;
        if (j < DD)            v = W1[(size_t)j * (2 * DD) + k];
        else if (j < 2 * DD)   v = W1[(size_t)(j - DD) * (2 * DD) + DD + k];
        else                   v = Wb[(size_t)(j - 2 * DD) * DD + k];
        g_Wcatb[i] = __float2bfloat16(v);
        return;
    }
    i -= R3;
    if (i < R4) g_W2b[i] = __float2bfloat16(W2[i]);
}
#define INIT_TOT (R0 + R1 + R2 + R3 + R4)

__global__ void k_zero_out(float* out) { if (threadIdx.x == 0) out[0] = 0.f; }

// ---------------- tensor-core helpers ----------------
__device__ __forceinline__ void mma16(float* c, const uint32_t* a, uint32_t b0, uint32_t b1) {
    asm volatile(
        "mma.sync.aligned.m16n8k16.row.col.f32.bf16.bf16.f32 "
        "{%0,%1,%2,%3},{%4,%5,%6,%7},{%8,%9},{%0,%1,%2,%3};"
        : "+f"(c[0]), "+f"(c[1]), "+f"(c[2]), "+f"(c[3])
        : "r"(a[0]), "r"(a[1]), "r"(a[2]), "r"(a[3]), "r"(b0), "r"(b1));
}
__device__ __forceinline__ void ldsm4(uint32_t* r, const bf16* p) {
    uint32_t a = (uint32_t)__cvta_generic_to_shared(p);
    asm volatile("ldmatrix.sync.aligned.m8n8.x4.shared.b16 {%0,%1,%2,%3}, [%4];"
        : "=r"(r[0]), "=r"(r[1]), "=r"(r[2]), "=r"(r[3]) : "r"(a));
}

// ---------------- bf16 GEMM v3b: 128x256 tile, 512 thr, 2-stage cp.async ---
//  C[m,n] = act( sum_k A[m,k]*W[n,k] + bias[n] ),  W bf16
//  AFP32=1: A fp32 (sync convert);  AFP32=0: A bf16 (cp.async)
//  requires: K % 64 == 0, N % 256 == 0, K/64 >= 2
//  dyn smem: 2 stages x (A 128x64 + B 256x64) bf16 = 98304 B
//  smem: row r, 16B-chunk c (0..7) stored at chunk (c ^ (r&7))
#define KC 64
#define A_ST (128 * KC)          // 8192 bf16
#define B_ST (256 * KC)          // 16384 bf16
#define ST (A_ST + B_ST)         // 24576 bf16 per stage
template<int AFP32>
__global__ __launch_bounds__(512) void k_gemm3(
    const void* __restrict__ Avoid, int lda,
    const bf16* __restrict__ W, int ldw,
    const float* __restrict__ bias,
    float* __restrict__ C, int ldc,
    int M, int N, int K, int doRelu)
{
    extern __shared__ bf16 sm[];
    const int tid = threadIdx.x;
    const int warp = tid >> 5, lane = tid & 31;
    const int m0 = blockIdx.y * 128, n0 = blockIdx.x * 256;
    const int wm = (warp >> 2) * 32;          // 4 m-warp groups x 32 rows
    const int wn = (warp & 3) * 64;           // 4 n-warp groups x 64 cols
    const int g = lane >> 2, tg = lane & 3;

    float acc[2][8][4];
    #pragma unroll
    for (int i = 0; i < 2; i++)
        #pragma unroll
        for (int j = 0; j < 8; j++)
            #pragma unroll
            for (int c = 0; c < 4; c++) acc[i][j][c] = 0.f;

    // A loader: 128 rows, 2 chunks/thread
    const int arow = tid >> 2;
    const int ac0 = (tid & 3) * 2;
    const int asw = arow & 7;
    // B loader: 256 rows, 4 chunks/thread
    const int brow = tid >> 1;
    const int bc0 = (tid & 1) * 4;
    const int bsw = brow & 7;

    const float* aF = (const float*)Avoid;
    const bf16*  aB = (const bf16*)Avoid;
    const int garow = m0 + arow;
    const bool aok = garow < M;
    const int arc = aok ? garow : 0;

    // fragment lane geometry
    const int ra = (lane & 7) + (lane & 8);
    const int ca = (lane >> 4) & 1;
    const int nboff = (lane & 7) + ((lane >> 4) & 1) * 8;
    const int cb = (lane >> 3) & 1;
    const int fsw = lane & 7;

    const int nk = K / KC;

    auto issue = [&](int kc) {
        int k0 = kc * KC;
        bf16* As = sm + (kc & 1) * ST;
        bf16* Bs = As + A_ST;
        if (AFP32) {
            #pragma unroll
            for (int j = 0; j < 2; j++) {
                int c = ac0 + j;
                float4 v0 = make_float4(0.f,0.f,0.f,0.f), v1 = v0;
                if (aok) {
                    const float* s = aF + (size_t)garow * lda + k0 + c * 8;
                    v0 = *(const float4*)s;
                    v1 = *(const float4*)(s + 4);
                }
                bf162* d = (bf162*)(As + arow * 64 + ((c ^ asw) * 8));
                d[0] = __floats2bfloat162_rn(v0.x, v0.y);
                d[1] = __floats2bfloat162_rn(v0.z, v0.w);
                d[2] = __floats2bfloat162_rn(v1.x, v1.y);
                d[3] = __floats2bfloat162_rn(v1.z, v1.w);
            }
        } else {
            #pragma unroll
            for (int j = 0; j < 2; j++) {
                int c = ac0 + j;
                const bf16* s = aB + (size_t)arc * lda + k0 + c * 8;
                uint32_t d = (uint32_t)__cvta_generic_to_shared(As + arow * 64 + ((c ^ asw) * 8));
                int sz = aok ? 16 : 0;
                asm volatile("cp.async.cg.shared.global [%0], [%1], 16, %2;"
                             :: "r"(d), "l"(s), "r"(sz));
            }
        }
        #pragma unroll
        for (int j = 0; j < 4; j++) {
            int c = bc0 + j;
            const bf16* s = W + (size_t)(n0 + brow) * ldw + k0 + c * 8;
            uint32_t d = (uint32_t)__cvta_generic_to_shared(Bs + brow * 64 + ((c ^ bsw) * 8));
            asm volatile("cp.async.cg.shared.global [%0], [%1], 16, 16;"
                         :: "r"(d), "l"(s));
        }
        asm volatile("cp.async.commit_group;");
    };

    issue(0);
    for (int kc = 0; kc < nk; kc++) {
        if (kc + 1 < nk) {
            issue(kc + 1);
            asm volatile("cp.async.wait_group 1;");
        } else {
            asm volatile("cp.async.wait_group 0;");
        }
        __syncthreads();
        const bf16* As = sm + (kc & 1) * ST;
        const bf16* Bs = As + A_ST;
        #pragma unroll
        for (int ks = 0; ks < 4; ks++) {
            int c0 = ks * 2;
            uint32_t a[2][4];
            #pragma unroll
            for (int mt = 0; mt < 2; mt++)
                ldsm4(a[mt], As + (wm + mt * 16 + ra) * 64 + (((c0 + ca) ^ fsw) * 8));
            uint32_t q[4][4];
            #pragma unroll
            for (int ntp = 0; ntp < 4; ntp++)
                ldsm4(q[ntp], Bs + (wn + ntp * 16 + nboff) * 64 + (((c0 + cb) ^ fsw) * 8));
            #pragma unroll
            for (int ntp = 0; ntp < 4; ntp++)
                #pragma unroll
                for (int h = 0; h < 2; h++)
                    #pragma unroll
                    for (int mt = 0; mt < 2; mt++)
                        mma16(acc[mt][ntp * 2 + h], a[mt], q[ntp][h * 2], q[ntp][h * 2 + 1]);
        }
        __syncthreads();
    }

    // epilogue: bias + optional relu
    #pragma unroll
    for (int mt = 0; mt < 2; mt++) {
        int r0 = m0 + wm + mt * 16 + g;
        #pragma unroll
        for (int nt = 0; nt < 8; nt++) {
            int cc = n0 + wn + nt * 8 + tg * 2;
            float bx = bias ? bias[cc] : 0.f;
            float by = bias ? bias[cc + 1] : 0.f;
            float v0 = acc[mt][nt][0] + bx, v1 = acc[mt][nt][1] + by;
            float v2 = acc[mt][nt][2] + bx, v3 = acc[mt][nt][3] + by;
            if (doRelu) {
                v0 = fmaxf(v0, 0.f); v1 = fmaxf(v1, 0.f);
                v2 = fmaxf(v2, 0.f); v3 = fmaxf(v3, 0.f);
            }
            if (r0 < M)     *(float2*)(C + (size_t)r0 * ldc + cc)       = make_float2(v0, v1);
            if (r0 + 8 < M) *(float2*)(C + (size_t)(r0 + 8) * ldc + cc) = make_float2(v2, v3);
        }
    }
}

// ---------------- per-combo combine (warp-per-row) ----------------
__global__ __launch_bounds__(256) void k_comb_inside(int L, int ns, int M,
                                                     const float* __restrict__ b1) {
    int w = threadIdx.x >> 5, lane = threadIdx.x & 31;
    int rid = blockIdx.x * 8 + w;
    if (rid >= M) return;
    int batch = rid % BB;
    int t = rid / BB;
    int si = t % ns, b = t / ns;
    int s = si + 1;
    int il = offL(s) + b;
    int ir = offL(L - s) + b + s;
    const float4* pl = (const float4*)(g_P + ((size_t)il * BB + batch) * 3 * DD);
    const float4* pr = (const float4*)(g_P + ((size_t)ir * BB + batch) * 3 * DD);
    const float4* xl = (const float4*)(g_iv + ((size_t)il * BB + batch) * DD);
    const float4* b14 = (const float4*)b1;
    bf162* hrow = (bf162*)(g_Hb + (size_t)rid * DD);
    float dot = 0.f;
    #pragma unroll
    for (int i = 0; i < 6; i++) {
        int e = lane + 32 * i;
        float4 a  = pl[e];
        float4 bb = pr[DD / 4 + e];
        float4 r  = pr[2 * (DD / 4) + e];
        float4 x  = xl[e];
        float4 bv = b14[e];
        float h0 = fmaxf(a.x + bb.x + bv.x, 0.f);
        float h1 = fmaxf(a.y + bb.y + bv.y, 0.f);
        float h2 = fmaxf(a.z + bb.z + bv.z, 0.f);
        float h3 = fmaxf(a.w + bb.w + bv.w, 0.f);
        hrow[2 * e]     = __floats2bfloat162_rn(h0, h1);
        hrow[2 * e + 1] = __floats2bfloat162_rn(h2, h3);
        dot += x.x * r.x + x.y * r.y + x.z * r.z + x.w * r.w;
    }
    #pragma unroll
    for (int o = 16; o; o >>= 1) dot += __shfl_down_sync(0xffffffffu, dot, o);
    if (lane == 0)
        g_S[rid] = dot + g_isc[il * BB + batch] + g_isc[ir * BB + batch];
}

__global__ __launch_bounds__(256) void k_comb_outside(int L, int nso, int M,
                                                      const float* __restrict__ b1) {
    int w = threadIdx.x >> 5, lane = threadIdx.x & 31;
    int rid = blockIdx.x * 8 + w;
    if (rid >= M) return;
    int batch = rid % BB;
    int t = rid / BB;
    int k = t % nso, b = t / nso;
    int ip, isx;
    if (k < b) {
        int c = k;
        ip  = offL(b + L - c) + c;
        isx = offL(b - c) + c;
    } else {
        int c = b + L + 1 + (k - b);
        ip  = offL(c - b) + b;
        isx = offL(c - b - L) + b + L;
    }
    const float4* pl = (const float4*)(g_Po + ((size_t)ip * BB + batch) * DD);
    const float4* pr = (const float4*)(g_P + ((size_t)isx * BB + batch) * 3 * DD);
    const float4* xp = (const float4*)(g_ov + ((size_t)ip * BB + batch) * DD);
    const float4* b14 = (const float4*)b1;
    bf162* hrow = (bf162*)(g_Hb + (size_t)rid * DD);
    float dot = 0.f;
    #pragma unroll
    for (int i = 0; i < 6; i++) {
        int e = lane + 32 * i;
        float4 a  = pl[e];
        float4 bb = pr[DD / 4 + e];
        float4 r  = pr[2 * (DD / 4) + e];
        float4 x  = xp[e];
        float4 bv = b14[e];
        float h0 = fmaxf(a.x + bb.x + bv.x, 0.f);
        float h1 = fmaxf(a.y + bb.y + bv.y, 0.f);
        float h2 = fmaxf(a.z + bb.z + bv.z, 0.f);
        float h3 = fmaxf(a.w + bb.w + bv.w, 0.f);
        hrow[2 * e]     = __floats2bfloat162_rn(h0, h1);
        hrow[2 * e + 1] = __floats2bfloat162_rn(h2, h3);
        dot += x.x * r.x + x.y * r.y + x.z * r.z + x.w * r.w;
    }
    #pragma unroll
    for (int o = 16; o; o >>= 1) dot += __shfl_down_sync(0xffffffffu, dot, o);
    if (lane == 0)
        g_S[rid] = dot + g_osc[ip * BB + batch] + g_isc[isx * BB + batch];
}

// ---------------- softmax over splits + weighted mix into chart cell
__global__ __launch_bounds__(256) void k_smx(int ns, int cell0,
                                             const float* __restrict__ V,
                                             float* __restrict__ vout,
                                             float* __restrict__ scout) {
    int bid = blockIdx.x;
    int batch = bid % BB;
    int b = bid / BB;
    __shared__ float sv[40], wv[40];
    int base = (b * ns) * BB + batch;
    if (threadIdx.x < ns) sv[threadIdx.x] = g_S[base + threadIdx.x * BB];
    __syncthreads();
    if (threadIdx.x == 0) {
        float mx = -1e30f;
        for (int s = 0; s < ns; s++) mx = fmaxf(mx, sv[s]);
        float Z = 0.f;
        for (int s = 0; s < ns; s++) { float e = expf(sv[s] - mx); wv[s] = e; Z += e; }
        float inv = 1.f / Z, sc = 0.f;
        for (int s = 0; s < ns; s++) { wv[s] *= inv; sc += wv[s] * sv[s]; }
        scout[(cell0 + b) * BB + batch] = sc;
    }
    __syncthreads();
    float* orow = vout + ((size_t)(cell0 + b) * BB + batch) * DD;
    for (int d = threadIdx.x; d < DD; d += 256) {
        float acc = 0.f;
        for (int s = 0; s < ns; s++)
            acc += wv[s] * V[(size_t)(base + s * BB) * DD + d];
        orow[d] = acc;
    }
}

// ---------------- final cosine loss ----------------
__global__ __launch_bounds__(256) void k_loss(const float* __restrict__ base,
                                              float* __restrict__ out) {
    int bid = blockIdx.x;
    int batch = bid % BB;
    int n = bid / BB;
    const float* tv = g_ov + ((size_t)n * BB + batch) * DD;
    const float* bv = base + ((size_t)n * BB + batch) * DD;
    float dp = 0.f, n1 = 0.f, n2 = 0.f;
    for (int d = threadIdx.x; d < DD; d += 256) {
        float a = tv[d], c = bv[d];
        dp += a * c; n1 += a * a; n2 += c * c;
    }
    dp = blockReduce256(dp);
    n1 = blockReduce256(n1);
    n2 = blockReduce256(n2);
    if (threadIdx.x == 0) {
        float den = fmaxf(sqrtf(n1) * sqrtf(n2), 1e-8f);
        atomicAdd(out, (1.f - dp / den) * (1.f / (NN * BB)));
    }
}

// ---------------- host launcher ----------------
extern "C" void kernel_launch(void* const* d_in, const int* in_sizes, int n_in,
                              void* d_out, int out_size) {
    const float* base = (const float*)d_in[0];
    const float* Wbil = (const float*)d_in[1];
    const float* W1   = (const float*)d_in[2];
    const float* b1   = (const float*)d_in[3];
    const float* W2   = (const float*)d_in[4];
    const float* b2   = (const float*)d_in[5];
    const float* rootb= (const float*)d_in[6];
    float* out = (float*)d_out;

    const int SMEM = 2 * ST * 2;   // 98304 bytes
    cudaFuncSetAttribute(k_gemm3<0>, cudaFuncAttributeMaxDynamicSharedMemorySize, SMEM);
    cudaFuncSetAttribute(k_gemm3<1>, cudaFuncAttributeMaxDynamicSharedMemorySize, SMEM);

    float *p_iv, *p_ov, *p_P, *p_Po, *p_V, *p_isc, *p_osc;
    bf16 *p_Hb, *p_Wcatb, *p_W2b;
    cudaGetSymbolAddress((void**)&p_iv,  g_iv);
    cudaGetSymbolAddress((void**)&p_ov,  g_ov);
    cudaGetSymbolAddress((void**)&p_P,   g_P);
    cudaGetSymbolAddress((void**)&p_Po,  g_Po);
    cudaGetSymbolAddress((void**)&p_Hb,  g_Hb);
    cudaGetSymbolAddress((void**)&p_V,   g_V);
    cudaGetSymbolAddress((void**)&p_Wcatb, g_Wcatb);
    cudaGetSymbolAddress((void**)&p_W2b,   g_W2b);
    cudaGetSymbolAddress((void**)&p_isc, g_isc);
    cudaGetSymbolAddress((void**)&p_osc, g_osc);

    k_init<<<(INIT_TOT + 255) / 256, 256>>>(base, rootb, W1, Wbil, W2);

    // projections for base cells (M = NN*BB = 1280)
    k_gemm3<1><<<dim3(9, 10), 512, SMEM>>>(
        p_iv, DD, p_Wcatb, DD, nullptr, p_P, 3 * DD, NN * BB, 3 * DD, DD, 0);

    // ---------------- inside pass ----------------
    for (int L = 2; L <= NN; L++) {
        int nb = NN + 1 - L, ns = L - 1;
        int M = nb * ns * BB;
        k_comb_inside<<<(M + 7) / 8, 256>>>(L, ns, M, b1);
        k_gemm3<0><<<dim3(3, (M + 127) / 128), 512, SMEM>>>(
            p_Hb, DD, p_W2b, DD, b2, p_V, DD, M, DD, DD, 1);
        k_smx<<<nb * BB, 256>>>(ns, offL(L), p_V, p_iv, p_isc);
        if (L < NN) {
            size_t c0 = (size_t)offL(L);
            k_gemm3<1><<<dim3(9, (nb * BB + 127) / 128), 512, SMEM>>>(
                p_iv + c0 * BB * DD, DD, p_Wcatb, DD, nullptr,
                p_P + c0 * BB * 3 * DD, 3 * DD, nb * BB, 3 * DD, DD, 0);
        }
    }

    // root outside projection Po = ov_root @ W1a^T
    {
        size_t c0 = (size_t)offL(NN);
        k_gemm3<1><<<dim3(3, 1), 512, SMEM>>>(
            p_ov + c0 * BB * DD, DD, p_Wcatb, DD, nullptr,
            p_Po + c0 * BB * DD, DD, BB, DD, DD, 0);
    }

    // ---------------- outside pass ----------------
    for (int L = NN - 1; L >= 1; L--) {
        int nb = NN + 1 - L, nso = NN - L;
        int M = nb * nso * BB;
        k_comb_outside<<<(M + 7) / 8, 256>>>(L, nso, M, b1);
        k_gemm3<0><<<dim3(3, (M + 127) / 128), 512, SMEM>>>(
            p_Hb, DD, p_W2b, DD, b2, p_V, DD, M, DD, DD, 1);
        k_smx<<<nb * BB, 256>>>(nso, offL(L), p_V, p_ov, p_osc);
        if (L > 1) {
            size_t c0 = (size_t)offL(L);
            k_gemm3<1><<<dim3(3, (nb * BB + 127) / 128), 512, SMEM>>>(
                p_ov + c0 * BB * DD, DD, p_Wcatb, DD, nullptr,
                p_Po + c0 * BB * DD, DD, nb * BB, DD, DD, 0);
        }
    }

    k_zero_out<<<1, 1>>>(out);
    k_loss<<<NN * BB, 256>>>(base, out);
}

// round 12
// speedup vs baseline: 1.2668x; 1.2668x over previous
#include <cuda_runtime.h>
#include <cuda_bf16.h>
#include <math.h>
#include <stdint.h>

#define NN 40
#define BB 32
#define DD 768
#define TT 820
#define MAXM 49920   // outside L=1: 40*39*32 combos

typedef __nv_bfloat16 bf16;
typedef __nv_bfloat162 bf162;

// ---------------- static scratch (no allocations allowed) ----------------
__device__ bf16  g_iv [(size_t)TT * BB * DD];        // inside vectors (bf16)
__device__ bf16  g_ov [(size_t)TT * BB * DD];        // outside vectors (bf16)
__device__ float g_isc[TT * BB];                     // inside scores
__device__ float g_osc[TT * BB];                     // outside scores
__device__ bf16  g_P  [(size_t)TT * BB * 3 * DD];    // [Pl | Pr | R] per cell/batch (bf16)
__device__ bf16  g_Po [(size_t)TT * BB * DD];        // ov @ W1a^T (bf16)
__device__ bf16  g_Hb [(size_t)MAXM * DD];           // hidden scratch (bf16)
__device__ bf16  g_V  [(size_t)MAXM * DD];           // compose output scratch (bf16)
__device__ float g_S  [MAXM];                        // scores scratch
__device__ bf16  g_Wcatb[3 * DD * DD];               // bf16 rows: W1a | W1b | W_bil
__device__ bf16  g_W2b  [DD * DD];                   // bf16 W2

__host__ __device__ __forceinline__ int offL(int L) {
    return TT - (42 - L) * (41 - L) / 2;   // first chart index of spans of length L
}

__device__ __forceinline__ float blockReduce256(float v) {
    __shared__ float sh[8];
    int lane = threadIdx.x & 31, w = threadIdx.x >> 5;
    #pragma unroll
    for (int o = 16; o; o >>= 1) v += __shfl_down_sync(0xffffffffu, v, o);
    __syncthreads();
    if (lane == 0) sh[w] = v;
    __syncthreads();
    if (threadIdx.x == 0) {
        float s = 0.f;
        #pragma unroll
        for (int i = 0; i < 8; i++) s += sh[i];
        v = s;
    }
    __syncthreads();
    return v;
}

__device__ __forceinline__ float2 bf2f(uint32_t u) {
    return __bfloat1622float2(*(const bf162*)&u);
}

// ---------------- merged init kernel ----------------
#define R0 (TT * BB)                 // isc/osc zero
#define R1 (NN * BB * DD)            // copy base -> iv (bf16)
#define R2 (BB * DD)                 // root bias -> ov[root] (bf16)
#define R3 (3 * DD * DD)             // Wcat build (bf16)
#define R4 (DD * DD)                 // W2 convert (bf16)
__global__ void k_init(const float* __restrict__ base, const float* __restrict__ rb,
                       const float* __restrict__ W1, const float* __restrict__ Wb,
                       const float* __restrict__ W2) {
    long long i = (long long)blockIdx.x * 256 + threadIdx.x;
    if (i < R0) { g_isc[i] = 0.f; g_osc[i] = 0.f; return; }
    i -= R0;
    if (i < R1) { g_iv[i] = __float2bfloat16(base[i]); return; }
    i -= R1;
    if (i < R2) { g_ov[(size_t)offL(NN) * BB * DD + i] = __float2bfloat16(rb[i % DD]); return; }
    i -= R2;
    if (i < R3) {
        int j = (int)(i / DD), k = (int)(i % DD);
        float v;
        if (j < DD)            v = W1[(size_t)j * (2 * DD) + k];
        else if (j < 2 * DD)   v = W1[(size_t)(j - DD) * (2 * DD) + DD + k];
        else                   v = Wb[(size_t)(j - 2 * DD) * DD + k];
        g_Wcatb[i] = __float2bfloat16(v);
        return;
    }
    i -= R3;
    if (i < R4) g_W2b[i] = __float2bfloat16(W2[i]);
}
#define INIT_TOT (R0 + R1 + R2 + R3 + R4)

__global__ void k_zero_out(float* out) { if (threadIdx.x == 0) out[0] = 0.f; }

// ---------------- tensor-core helpers ----------------
__device__ __forceinline__ void mma16(float* c, const uint32_t* a, uint32_t b0, uint32_t b1) {
    asm volatile(
        "mma.sync.aligned.m16n8k16.row.col.f32.bf16.bf16.f32 "
        "{%0,%1,%2,%3},{%4,%5,%6,%7},{%8,%9},{%0,%1,%2,%3};"
        : "+f"(c[0]), "+f"(c[1]), "+f"(c[2]), "+f"(c[3])
        : "r"(a[0]), "r"(a[1]), "r"(a[2]), "r"(a[3]), "r"(b0), "r"(b1));
}
__device__ __forceinline__ void ldsm4(uint32_t* r, const bf16* p) {
    uint32_t a = (uint32_t)__cvta_generic_to_shared(p);
    asm volatile("ldmatrix.sync.aligned.m8n8.x4.shared.b16 {%0,%1,%2,%3}, [%4];"
        : "=r"(r[0]), "=r"(r[1]), "=r"(r[2]), "=r"(r[3]) : "r"(a));
}

// ============ GEMM A: 128x128 tile, 256 thr, 2-stage (proven round-8) =====
//  C[m,n] = act( sum_k A[m,k]*W[n,k] + bias[n] ),  A,W bf16, C bf16 out
//  requires: K % 64 == 0, N % 128 == 0
//  dyn smem: 2 x (A 128x64 + B 128x64) bf16 = 65536 B
#define KC 64
__global__ __launch_bounds__(256) void k_gemmA(
    const bf16* __restrict__ A, int lda,
    const bf16* __restrict__ W, int ldw,
    const float* __restrict__ bias,
    bf16* __restrict__ C, int ldc,
    int M, int N, int K, int doRelu)
{
    extern __shared__ bf16 sm[];
    const int tid = threadIdx.x;
    const int warp = tid >> 5, lane = tid & 31;
    const int m0 = blockIdx.y * 128, n0 = blockIdx.x * 128;
    const int wm = (warp >> 2) * 64, wn = (warp & 3) * 32;
    const int g = lane >> 2, tg = lane & 3;

    float acc[4][4][4];
    #pragma unroll
    for (int i = 0; i < 4; i++)
        #pragma unroll
        for (int j = 0; j < 4; j++)
            #pragma unroll
            for (int c = 0; c < 4; c++) acc[i][j][c] = 0.f;

    const int lrow = tid >> 1;
    const int cbase = (tid & 1) * 4;
    const int lsw = lrow & 7;
    const int arow = m0 + lrow;
    const bool aok = arow < M;
    const int arc = aok ? arow : 0;

    const int ra = (lane & 7) + (lane & 8);
    const int ca = (lane >> 4) & 1;
    const int nboff = (lane & 7) + ((lane >> 4) & 1) * 8;
    const int cb = (lane >> 3) & 1;
    const int fsw = lane & 7;

    const int nk = K / KC;

    auto issue = [&](int kc) {
        int k0 = kc * KC;
        bf16* As = sm + (kc & 1) * 16384;
        bf16* Bs = As + 8192;
        #pragma unroll
        for (int j = 0; j < 4; j++) {
            int c = cbase + j;
            const bf16* s = A + (size_t)arc * lda + k0 + c * 8;
            uint32_t d = (uint32_t)__cvta_generic_to_shared(As + lrow * 64 + ((c ^ lsw) * 8));
            int sz = aok ? 16 : 0;
            asm volatile("cp.async.cg.shared.global [%0], [%1], 16, %2;"
                         :: "r"(d), "l"(s), "r"(sz));
        }
        #pragma unroll
        for (int j = 0; j < 4; j++) {
            int c = cbase + j;
            const bf16* s = W + (size_t)(n0 + lrow) * ldw + k0 + c * 8;
            uint32_t d = (uint32_t)__cvta_generic_to_shared(Bs + lrow * 64 + ((c ^ lsw) * 8));
            asm volatile("cp.async.cg.shared.global [%0], [%1], 16, 16;"
                         :: "r"(d), "l"(s));
        }
        asm volatile("cp.async.commit_group;");
    };

    issue(0);
    for (int kc = 0; kc < nk; kc++) {
        if (kc + 1 < nk) {
            issue(kc + 1);
            asm volatile("cp.async.wait_group 1;");
        } else {
            asm volatile("cp.async.wait_group 0;");
        }
        __syncthreads();
        const bf16* As = sm + (kc & 1) * 16384;
        const bf16* Bs = As + 8192;
        #pragma unroll
        for (int ks = 0; ks < 4; ks++) {
            int c0 = ks * 2;
            uint32_t a[4][4];
            #pragma unroll
            for (int mt = 0; mt < 4; mt++)
                ldsm4(a[mt], As + (wm + mt * 16 + ra) * 64 + (((c0 + ca) ^ fsw) * 8));
            uint32_t q[2][4];
            #pragma unroll
            for (int ntp = 0; ntp < 2; ntp++)
                ldsm4(q[ntp], Bs + (wn + ntp * 16 + nboff) * 64 + (((c0 + cb) ^ fsw) * 8));
            #pragma unroll
            for (int ntp = 0; ntp < 2; ntp++)
                #pragma unroll
                for (int h = 0; h < 2; h++)
                    #pragma unroll
                    for (int mt = 0; mt < 4; mt++)
                        mma16(acc[mt][ntp * 2 + h], a[mt], q[ntp][h * 2], q[ntp][h * 2 + 1]);
        }
        __syncthreads();
    }

    #pragma unroll
    for (int mt = 0; mt < 4; mt++) {
        int r0 = m0 + wm + mt * 16 + g;
        #pragma unroll
        for (int nt = 0; nt < 4; nt++) {
            int cc = n0 + wn + nt * 8 + tg * 2;
            float bx = bias ? bias[cc] : 0.f;
            float by = bias ? bias[cc + 1] : 0.f;
            float v0 = acc[mt][nt][0] + bx, v1 = acc[mt][nt][1] + by;
            float v2 = acc[mt][nt][2] + bx, v3 = acc[mt][nt][3] + by;
            if (doRelu) {
                v0 = fmaxf(v0, 0.f); v1 = fmaxf(v1, 0.f);
                v2 = fmaxf(v2, 0.f); v3 = fmaxf(v3, 0.f);
            }
            if (r0 < M)     *(bf162*)(C + (size_t)r0 * ldc + cc)       = __floats2bfloat162_rn(v0, v1);
            if (r0 + 8 < M) *(bf162*)(C + (size_t)(r0 + 8) * ldc + cc) = __floats2bfloat162_rn(v2, v3);
        }
    }
}

// ============ GEMM B: 128x256 tile, 512 thr, 2-stage (proven round-11) ====
//  requires: K % 64 == 0, N % 256 == 0; dyn smem 98304 B
#define A_ST (128 * KC)
#define B_ST (256 * KC)
#define ST (A_ST + B_ST)
__global__ __launch_bounds__(512) void k_gemmB(
    const bf16* __restrict__ A, int lda,
    const bf16* __restrict__ W, int ldw,
    const float* __restrict__ bias,
    bf16* __restrict__ C, int ldc,
    int M, int N, int K, int doRelu)
{
    extern __shared__ bf16 sm[];
    const int tid = threadIdx.x;
    const int warp = tid >> 5, lane = tid & 31;
    const int m0 = blockIdx.y * 128, n0 = blockIdx.x * 256;
    const int wm = (warp >> 2) * 32;
    const int wn = (warp & 3) * 64;
    const int g = lane >> 2, tg = lane & 3;

    float acc[2][8][4];
    #pragma unroll
    for (int i = 0; i < 2; i++)
        #pragma unroll
        for (int j = 0; j < 8; j++)
            #pragma unroll
            for (int c = 0; c < 4; c++) acc[i][j][c] = 0.f;

    const int arow = tid >> 2;
    const int ac0 = (tid & 3) * 2;
    const int asw = arow & 7;
    const int brow = tid >> 1;
    const int bc0 = (tid & 1) * 4;
    const int bsw = brow & 7;

    const int garow = m0 + arow;
    const bool aok = garow < M;
    const int arc = aok ? garow : 0;

    const int ra = (lane & 7) + (lane & 8);
    const int ca = (lane >> 4) & 1;
    const int nboff = (lane & 7) + ((lane >> 4) & 1) * 8;
    const int cb = (lane >> 3) & 1;
    const int fsw = lane & 7;

    const int nk = K / KC;

    auto issue = [&](int kc) {
        int k0 = kc * KC;
        bf16* As = sm + (kc & 1) * ST;
        bf16* Bs = As + A_ST;
        #pragma unroll
        for (int j = 0; j < 2; j++) {
            int c = ac0 + j;
            const bf16* s = A + (size_t)arc * lda + k0 + c * 8;
            uint32_t d = (uint32_t)__cvta_generic_to_shared(As + arow * 64 + ((c ^ asw) * 8));
            int sz = aok ? 16 : 0;
            asm volatile("cp.async.cg.shared.global [%0], [%1], 16, %2;"
                         :: "r"(d), "l"(s), "r"(sz));
        }
        #pragma unroll
        for (int j = 0; j < 4; j++) {
            int c = bc0 + j;
            const bf16* s = W + (size_t)(n0 + brow) * ldw + k0 + c * 8;
            uint32_t d = (uint32_t)__cvta_generic_to_shared(Bs + brow * 64 + ((c ^ bsw) * 8));
            asm volatile("cp.async.cg.shared.global [%0], [%1], 16, 16;"
                         :: "r"(d), "l"(s));
        }
        asm volatile("cp.async.commit_group;");
    };

    issue(0);
    for (int kc = 0; kc < nk; kc++) {
        if (kc + 1 < nk) {
            issue(kc + 1);
            asm volatile("cp.async.wait_group 1;");
        } else {
            asm volatile("cp.async.wait_group 0;");
        }
        __syncthreads();
        const bf16* As = sm + (kc & 1) * ST;
        const bf16* Bs = As + A_ST;
        #pragma unroll
        for (int ks = 0; ks < 4; ks++) {
            int c0 = ks * 2;
            uint32_t a[2][4];
            #pragma unroll
            for (int mt = 0; mt < 2; mt++)
                ldsm4(a[mt], As + (wm + mt * 16 + ra) * 64 + (((c0 + ca) ^ fsw) * 8));
            uint32_t q[4][4];
            #pragma unroll
            for (int ntp = 0; ntp < 4; ntp++)
                ldsm4(q[ntp], Bs + (wn + ntp * 16 + nboff) * 64 + (((c0 + cb) ^ fsw) * 8));
            #pragma unroll
            for (int ntp = 0; ntp < 4; ntp++)
                #pragma unroll
                for (int h = 0; h < 2; h++)
                    #pragma unroll
                    for (int mt = 0; mt < 2; mt++)
                        mma16(acc[mt][ntp * 2 + h], a[mt], q[ntp][h * 2], q[ntp][h * 2 + 1]);
        }
        __syncthreads();
    }

    #pragma unroll
    for (int mt = 0; mt < 2; mt++) {
        int r0 = m0 + wm + mt * 16 + g;
        #pragma unroll
        for (int nt = 0; nt < 8; nt++) {
            int cc = n0 + wn + nt * 8 + tg * 2;
            float bx = bias ? bias[cc] : 0.f;
            float by = bias ? bias[cc + 1] : 0.f;
            float v0 = acc[mt][nt][0] + bx, v1 = acc[mt][nt][1] + by;
            float v2 = acc[mt][nt][2] + bx, v3 = acc[mt][nt][3] + by;
            if (doRelu) {
                v0 = fmaxf(v0, 0.f); v1 = fmaxf(v1, 0.f);
                v2 = fmaxf(v2, 0.f); v3 = fmaxf(v3, 0.f);
            }
            if (r0 < M)     *(bf162*)(C + (size_t)r0 * ldc + cc)       = __floats2bfloat162_rn(v0, v1);
            if (r0 + 8 < M) *(bf162*)(C + (size_t)(r0 + 8) * ldc + cc) = __floats2bfloat162_rn(v2, v3);
        }
    }
}

// ---------------- per-combo combine (warp-per-row, bf16 IO) ----------------
__global__ __launch_bounds__(256) void k_comb_inside(int L, int ns, int M,
                                                     const float* __restrict__ b1) {
    int w = threadIdx.x >> 5, lane = threadIdx.x & 31;
    int rid = blockIdx.x * 8 + w;
    if (rid >= M) return;
    int batch = rid % BB;
    int t = rid / BB;
    int si = t % ns, b = t / ns;
    int s = si + 1;
    int il = offL(s) + b;
    int ir = offL(L - s) + b + s;
    const uint4* pl = (const uint4*)(g_P + ((size_t)il * BB + batch) * 3 * DD);
    const uint4* pr = (const uint4*)(g_P + ((size_t)ir * BB + batch) * 3 * DD);
    const uint4* xl = (const uint4*)(g_iv + ((size_t)il * BB + batch) * DD);
    const float4* b14 = (const float4*)b1;
    uint4* hrow = (uint4*)(g_Hb + (size_t)rid * DD);
    float dot = 0.f;
    #pragma unroll
    for (int i = 0; i < 3; i++) {
        int e = lane + 32 * i;            // uint4 idx (8 bf16), 96 per row
        uint4 a4 = pl[e];
        uint4 b4 = pr[DD / 8 + e];
        uint4 r4 = pr[2 * (DD / 8) + e];
        uint4 x4 = xl[e];
        float4 v0 = b14[2 * e], v1 = b14[2 * e + 1];
        float2 a0 = bf2f(a4.x), a1 = bf2f(a4.y), a2 = bf2f(a4.z), a3 = bf2f(a4.w);
        float2 c0 = bf2f(b4.x), c1 = bf2f(b4.y), c2 = bf2f(b4.z), c3 = bf2f(b4.w);
        float2 r0 = bf2f(r4.x), r1 = bf2f(r4.y), r2 = bf2f(r4.z), r3 = bf2f(r4.w);
        float2 x0 = bf2f(x4.x), x1 = bf2f(x4.y), x2 = bf2f(x4.z), x3 = bf2f(x4.w);
        uint4 o;
        *(bf162*)&o.x = __floats2bfloat162_rn(fmaxf(a0.x + c0.x + v0.x, 0.f), fmaxf(a0.y + c0.y + v0.y, 0.f));
        *(bf162*)&o.y = __floats2bfloat162_rn(fmaxf(a1.x + c1.x + v0.z, 0.f), fmaxf(a1.y + c1.y + v0.w, 0.f));
        *(bf162*)&o.z = __floats2bfloat162_rn(fmaxf(a2.x + c2.x + v1.x, 0.f), fmaxf(a2.y + c2.y + v1.y, 0.f));
        *(bf162*)&o.w = __floats2bfloat162_rn(fmaxf(a3.x + c3.x + v1.z, 0.f), fmaxf(a3.y + c3.y + v1.w, 0.f));
        hrow[e] = o;
        dot += x0.x * r0.x + x0.y * r0.y + x1.x * r1.x + x1.y * r1.y
             + x2.x * r2.x + x2.y * r2.y + x3.x * r3.x + x3.y * r3.y;
    }
    #pragma unroll
    for (int o = 16; o; o >>= 1) dot += __shfl_down_sync(0xffffffffu, dot, o);
    if (lane == 0)
        g_S[rid] = dot + g_isc[il * BB + batch] + g_isc[ir * BB + batch];
}

__global__ __launch_bounds__(256) void k_comb_outside(int L, int nso, int M,
                                                      const float* __restrict__ b1) {
    int w = threadIdx.x >> 5, lane = threadIdx.x & 31;
    int rid = blockIdx.x * 8 + w;
    if (rid >= M) return;
    int batch = rid % BB;
    int t = rid / BB;
    int k = t % nso, b = t / nso;
    int ip, isx;
    if (k < b) {
        int c = k;
        ip  = offL(b + L - c) + c;
        isx = offL(b - c) + c;
    } else {
        int c = b + L + 1 + (k - b);
        ip  = offL(c - b) + b;
        isx = offL(c - b - L) + b + L;
    }
    const uint4* pl = (const uint4*)(g_Po + ((size_t)ip * BB + batch) * DD);
    const uint4* pr = (const uint4*)(g_P + ((size_t)isx * BB + batch) * 3 * DD);
    const uint4* xp = (const uint4*)(g_ov + ((size_t)ip * BB + batch) * DD);
    const float4* b14 = (const float4*)b1;
    uint4* hrow = (uint4*)(g_Hb + (size_t)rid * DD);
    float dot = 0.f;
    #pragma unroll
    for (int i = 0; i < 3; i++) {
        int e = lane + 32 * i;
        uint4 a4 = pl[e];
        uint4 b4 = pr[DD / 8 + e];
        uint4 r4 = pr[2 * (DD / 8) + e];
        uint4 x4 = xp[e];
        float4 v0 = b14[2 * e], v1 = b14[2 * e + 1];
        float2 a0 = bf2f(a4.x), a1 = bf2f(a4.y), a2 = bf2f(a4.z), a3 = bf2f(a4.w);
        float2 c0 = bf2f(b4.x), c1 = bf2f(b4.y), c2 = bf2f(b4.z), c3 = bf2f(b4.w);
        float2 r0 = bf2f(r4.x), r1 = bf2f(r4.y), r2 = bf2f(r4.z), r3 = bf2f(r4.w);
        float2 x0 = bf2f(x4.x), x1 = bf2f(x4.y), x2 = bf2f(x4.z), x3 = bf2f(x4.w);
        uint4 o;
        *(bf162*)&o.x = __floats2bfloat162_rn(fmaxf(a0.x + c0.x + v0.x, 0.f), fmaxf(a0.y + c0.y + v0.y, 0.f));
        *(bf162*)&o.y = __floats2bfloat162_rn(fmaxf(a1.x + c1.x + v0.z, 0.f), fmaxf(a1.y + c1.y + v0.w, 0.f));
        *(bf162*)&o.z = __floats2bfloat162_rn(fmaxf(a2.x + c2.x + v1.x, 0.f), fmaxf(a2.y + c2.y + v1.y, 0.f));
        *(bf162*)&o.w = __floats2bfloat162_rn(fmaxf(a3.x + c3.x + v1.z, 0.f), fmaxf(a3.y + c3.y + v1.w, 0.f));
        hrow[e] = o;
        dot += x0.x * r0.x + x0.y * r0.y + x1.x * r1.x + x1.y * r1.y
             + x2.x * r2.x + x2.y * r2.y + x3.x * r3.x + x3.y * r3.y;
    }
    #pragma unroll
    for (int o = 16; o; o >>= 1) dot += __shfl_down_sync(0xffffffffu, dot, o);
    if (lane == 0)
        g_S[rid] = dot + g_osc[ip * BB + batch] + g_isc[isx * BB + batch];
}

// ---------------- softmax over splits + weighted mix into chart cell ------
__global__ __launch_bounds__(256) void k_smx(int ns, int cell0,
                                             const bf16* __restrict__ V,
                                             bf16* __restrict__ vout,
                                             float* __restrict__ scout) {
    int bid = blockIdx.x;
    int batch = bid % BB;
    int b = bid / BB;
    __shared__ float sv[40], wv[40];
    int base = (b * ns) * BB + batch;
    if (threadIdx.x < ns) sv[threadIdx.x] = g_S[base + threadIdx.x * BB];
    __syncthreads();
    if (threadIdx.x == 0) {
        float mx = -1e30f;
        for (int s = 0; s < ns; s++) mx = fmaxf(mx, sv[s]);
        float Z = 0.f;
        for (int s = 0; s < ns; s++) { float e = expf(sv[s] - mx); wv[s] = e; Z += e; }
        float inv = 1.f / Z, sc = 0.f;
        for (int s = 0; s < ns; s++) { wv[s] *= inv; sc += wv[s] * sv[s]; }
        scout[(cell0 + b) * BB + batch] = sc;
    }
    __syncthreads();
    bf16* orow = vout + ((size_t)(cell0 + b) * BB + batch) * DD;
    for (int d = threadIdx.x; d < DD; d += 256) {
        float acc = 0.f;
        for (int s = 0; s < ns; s++)
            acc += wv[s] * __bfloat162float(V[(size_t)(base + s * BB) * DD + d]);
        orow[d] = __float2bfloat16(acc);
    }
}

// ---------------- final cosine loss ----------------
__global__ __launch_bounds__(256) void k_loss(const float* __restrict__ base,
                                              float* __restrict__ out) {
    int bid = blockIdx.x;
    int batch = bid % BB;
    int n = bid / BB;
    const bf16* tv = g_ov + ((size_t)n * BB + batch) * DD;
    const float* bv = base + ((size_t)n * BB + batch) * DD;
    float dp = 0.f, n1 = 0.f, n2 = 0.f;
    for (int d = threadIdx.x; d < DD; d += 256) {
        float a = __bfloat162float(tv[d]), c = bv[d];
        dp += a * c; n1 += a * a; n2 += c * c;
    }
    dp = blockReduce256(dp);
    n1 = blockReduce256(n1);
    n2 = blockReduce256(n2);
    if (threadIdx.x == 0) {
        float den = fmaxf(sqrtf(n1) * sqrtf(n2), 1e-8f);
        atomicAdd(out, (1.f - dp / den) * (1.f / (NN * BB)));
    }
}

// ---------------- host launcher ----------------
static inline void launch_gemm(const bf16* A, int lda, const bf16* W, int ldw,
                               const float* bias, bf16* C, int ldc,
                               int M, int N, int K, int doRelu) {
    if (M >= 8192 && (N % 256) == 0) {
        k_gemmB<<<dim3(N / 256, (M + 127) / 128), 512, 98304>>>(
            A, lda, W, ldw, bias, C, ldc, M, N, K, doRelu);
    } else {
        k_gemmA<<<dim3(N / 128, (M + 127) / 128), 256, 65536>>>(
            A, lda, W, ldw, bias, C, ldc, M, N, K, doRelu);
    }
}

extern "C" void kernel_launch(void* const* d_in, const int* in_sizes, int n_in,
                              void* d_out, int out_size) {
    const float* base = (const float*)d_in[0];
    const float* Wbil = (const float*)d_in[1];
    const float* W1   = (const float*)d_in[2];
    const float* b1   = (const float*)d_in[3];
    const float* W2   = (const float*)d_in[4];
    const float* b2   = (const float*)d_in[5];
    const float* rootb= (const float*)d_in[6];
    float* out = (float*)d_out;

    cudaFuncSetAttribute(k_gemmA, cudaFuncAttributeMaxDynamicSharedMemorySize, 65536);
    cudaFuncSetAttribute(k_gemmB, cudaFuncAttributeMaxDynamicSharedMemorySize, 98304);

    bf16 *p_iv, *p_ov, *p_P, *p_Po, *p_V, *p_Hb, *p_Wcatb, *p_W2b;
    float *p_isc, *p_osc;
    cudaGetSymbolAddress((void**)&p_iv,  g_iv);
    cudaGetSymbolAddress((void**)&p_ov,  g_ov);
    cudaGetSymbolAddress((void**)&p_P,   g_P);
    cudaGetSymbolAddress((void**)&p_Po,  g_Po);
    cudaGetSymbolAddress((void**)&p_Hb,  g_Hb);
    cudaGetSymbolAddress((void**)&p_V,   g_V);
    cudaGetSymbolAddress((void**)&p_Wcatb, g_Wcatb);
    cudaGetSymbolAddress((void**)&p_W2b,   g_W2b);
    cudaGetSymbolAddress((void**)&p_isc, g_isc);
    cudaGetSymbolAddress((void**)&p_osc, g_osc);

    k_init<<<(INIT_TOT + 255) / 256, 256>>>(base, rootb, W1, Wbil, W2);

    // projections for base cells (M = 1280)
    launch_gemm(p_iv, DD, p_Wcatb, DD, nullptr, p_P, 3 * DD, NN * BB, 3 * DD, DD, 0);

    // ---------------- inside pass ----------------
    for (int L = 2; L <= NN; L++) {
        int nb = NN + 1 - L, ns = L - 1;
        int M = nb * ns * BB;
        k_comb_inside<<<(M + 7) / 8, 256>>>(L, ns, M, b1);
        launch_gemm(p_Hb, DD, p_W2b, DD, b2, p_V, DD, M, DD, DD, 1);
        k_smx<<<nb * BB, 256>>>(ns, offL(L), p_V, p_iv, p_isc);
        if (L < NN) {
            size_t c0 = (size_t)offL(L);
            launch_gemm(p_iv + c0 * BB * DD, DD, p_Wcatb, DD, nullptr,
                        p_P + c0 * BB * 3 * DD, 3 * DD, nb * BB, 3 * DD, DD, 0);
        }
    }

    // root outside projection Po = ov_root @ W1a^T
    {
        size_t c0 = (size_t)offL(NN);
        launch_gemm(p_ov + c0 * BB * DD, DD, p_Wcatb, DD, nullptr,
                    p_Po + c0 * BB * DD, DD, BB, DD, DD, 0);
    }

    // ---------------- outside pass ----------------
    for (int L = NN - 1; L >= 1; L--) {
        int nb = NN + 1 - L, nso = NN - L;
        int M = nb * nso * BB;
        k_comb_outside<<<(M + 7) / 8, 256>>>(L, nso, M, b1);
        launch_gemm(p_Hb, DD, p_W2b, DD, b2, p_V, DD, M, DD, DD, 1);
        k_smx<<<nb * BB, 256>>>(nso, offL(L), p_V, p_ov, p_osc);
        if (L > 1) {
            size_t c0 = (size_t)offL(L);
            launch_gemm(p_ov + c0 * BB * DD, DD, p_Wcatb, DD, nullptr,
                        p_Po + c0 * BB * DD, DD, nb * BB, DD, DD, 0);
        }
    }

    k_zero_out<<<1, 1>>>(out);
    k_loss<<<NN * BB, 256>>>(base, out);
}

// round 14
// speedup vs baseline: 1.3276x; 1.0480x over previous
#include <cuda_runtime.h>
#include <cuda_bf16.h>
#include <math.h>
#include <stdint.h>

#define NN 40
#define BB 32
#define DD 768
#define TT 820
#define MAXM 49920   // outside L=1: 40*39*32 combos

typedef __nv_bfloat16 bf16;
typedef __nv_bfloat162 bf162;

// ---------------- static scratch (no allocations allowed) ----------------
__device__ bf16  g_iv [(size_t)TT * BB * DD];        // inside vectors (bf16)
__device__ bf16  g_ov [(size_t)TT * BB * DD];        // outside vectors (bf16)
__device__ float g_isc[TT * BB];                     // inside scores
__device__ float g_osc[TT * BB];                     // outside scores
__device__ bf16  g_P  [(size_t)TT * BB * 3 * DD];    // [Pl | Pr | R] per cell/batch (bf16)
__device__ bf16  g_Po [(size_t)TT * BB * DD];        // ov @ W1a^T (bf16)
__device__ bf16  g_Hb [(size_t)MAXM * DD];           // hidden scratch (bf16)
__device__ bf16  g_V  [(size_t)MAXM * DD];           // compose output scratch (bf16)
__device__ float g_S  [MAXM];                        // scores scratch
__device__ bf16  g_Wcatb[3 * DD * DD];               // bf16 rows: W1a | W1b | W_bil
__device__ bf16  g_W2b  [DD * DD];                   // bf16 W2

__host__ __device__ __forceinline__ int offL(int L) {
    return TT - (42 - L) * (41 - L) / 2;   // first chart index of spans of length L
}

__device__ __forceinline__ float blockReduce256(float v) {
    __shared__ float sh[8];
    int lane = threadIdx.x & 31, w = threadIdx.x >> 5;
    #pragma unroll
    for (int o = 16; o; o >>= 1) v += __shfl_down_sync(0xffffffffu, v, o);
    __syncthreads();
    if (lane == 0) sh[w] = v;
    __syncthreads();
    if (threadIdx.x == 0) {
        float s = 0.f;
        #pragma unroll
        for (int i = 0; i < 8; i++) s += sh[i];
        v = s;
    }
    __syncthreads();
    return v;
}

__device__ __forceinline__ float2 bf2f(uint32_t u) {
    return __bfloat1622float2(*(const bf162*)&u);
}

// ---------------- merged init kernel (also zeroes the output scalar) ------
#define R0 (TT * BB)
#define R1 (NN * BB * DD)
#define R2 (BB * DD)
#define R3 (3 * DD * DD)
#define R4 (DD * DD)
__global__ void k_init(const float* __restrict__ base, const float* __restrict__ rb,
                       const float* __restrict__ W1, const float* __restrict__ Wb,
                       const float* __restrict__ W2, float* __restrict__ out) {
    long long i = (long long)blockIdx.x * 256 + threadIdx.x;
    if (i == 0) out[0] = 0.f;
    if (i < R0) { g_isc[i] = 0.f; g_osc[i] = 0.f; return; }
    i -= R0;
    if (i < R1) { g_iv[i] = __float2bfloat16(base[i]); return; }
    i -= R1;
    if (i < R2) { g_ov[(size_t)offL(NN) * BB * DD + i] = __float2bfloat16(rb[i % DD]); return; }
    i -= R2;
    if (i < R3) {
        int j = (int)(i / DD), k = (int)(i % DD);
        float v;
        if (j < DD)            v = W1[(size_t)j * (2 * DD) + k];
        else if (j < 2 * DD)   v = W1[(size_t)(j - DD) * (2 * DD) + DD + k];
        else                   v = Wb[(size_t)(j - 2 * DD) * DD + k];
        g_Wcatb[i] = __float2bfloat16(v);
        return;
    }
    i -= R3;
    if (i < R4) g_W2b[i] = __float2bfloat16(W2[i]);
}
#define INIT_TOT (R0 + R1 + R2 + R3 + R4)

// ---------------- tensor-core helpers ----------------
__device__ __forceinline__ void mma16(float* c, const uint32_t* a, uint32_t b0, uint32_t b1) {
    asm volatile(
        "mma.sync.aligned.m16n8k16.row.col.f32.bf16.bf16.f32 "
        "{%0,%1,%2,%3},{%4,%5,%6,%7},{%8,%9},{%0,%1,%2,%3};"
        : "+f"(c[0]), "+f"(c[1]), "+f"(c[2]), "+f"(c[3])
        : "r"(a[0]), "r"(a[1]), "r"(a[2]), "r"(a[3]), "r"(b0), "r"(b1));
}
__device__ __forceinline__ void ldsm4(uint32_t* r, const bf16* p) {
    uint32_t a = (uint32_t)__cvta_generic_to_shared(p);
    asm volatile("ldmatrix.sync.aligned.m8n8.x4.shared.b16 {%0,%1,%2,%3}, [%4];"
        : "=r"(r[0]), "=r"(r[1]), "=r"(r[2]), "=r"(r[3]) : "r"(a));
}

#define KC 64

// ============ GEMM C: 64x128 tile, 256 thr, 3-stage cp.async ==============
//  for small M (better SM coverage).  dyn smem: 3 x (64+128)x64 bf16 = 73728 B
#define CA_ST (64 * KC)            // 4096 bf16
#define CB_ST (128 * KC)           // 8192 bf16
#define CST (CA_ST + CB_ST)        // 12288 bf16 per stage
__global__ __launch_bounds__(256) void k_gemmC(
    const bf16* __restrict__ A, int lda,
    const bf16* __restrict__ W, int ldw,
    const float* __restrict__ bias,
    bf16* __restrict__ C, int ldc,
    int M, int N, int K, int doRelu)
{
    extern __shared__ bf16 sm[];
    const int tid = threadIdx.x;
    const int warp = tid >> 5, lane = tid & 31;
    const int m0 = blockIdx.y * 64, n0 = blockIdx.x * 128;
    const int wm = (warp >> 2) * 32;          // 2 m-groups x 32 rows
    const int wn = (warp & 3) * 32;           // 4 n-groups x 32 cols
    const int g = lane >> 2, tg = lane & 3;

    float acc[2][4][4];
    #pragma unroll
    for (int i = 0; i < 2; i++)
        #pragma unroll
        for (int j = 0; j < 4; j++)
            #pragma unroll
            for (int c = 0; c < 4; c++) acc[i][j][c] = 0.f;

    // A loader: 64 rows, 2 chunks/thread
    const int arow = tid >> 2;
    const int ac0 = (tid & 3) * 2;
    const int asw = arow & 7;
    // B loader: 128 rows, 4 chunks/thread
    const int brow = tid >> 1;
    const int bc0 = (tid & 1) * 4;
    const int bsw = brow & 7;

    const int garow = m0 + arow;
    const bool aok = garow < M;
    const int arc = aok ? garow : 0;

    const int ra = (lane & 7) + (lane & 8);
    const int ca = (lane >> 4) & 1;
    const int nboff = (lane & 7) + ((lane >> 4) & 1) * 8;
    const int cb = (lane >> 3) & 1;
    const int fsw = lane & 7;

    const int nk = K / KC;

    auto issue = [&](int kc) {
        int k0 = kc * KC;
        bf16* As = sm + (kc % 3) * CST;
        bf16* Bs = As + CA_ST;
        #pragma unroll
        for (int j = 0; j < 2; j++) {
            int c = ac0 + j;
            const bf16* s = A + (size_t)arc * lda + k0 + c * 8;
            uint32_t d = (uint32_t)__cvta_generic_to_shared(As + arow * 64 + ((c ^ asw) * 8));
            int sz = aok ? 16 : 0;
            asm volatile("cp.async.cg.shared.global [%0], [%1], 16, %2;"
                         :: "r"(d), "l"(s), "r"(sz));
        }
        #pragma unroll
        for (int j = 0; j < 4; j++) {
            int c = bc0 + j;
            const bf16* s = W + (size_t)(n0 + brow) * ldw + k0 + c * 8;
            uint32_t d = (uint32_t)__cvta_generic_to_shared(Bs + brow * 64 + ((c ^ bsw) * 8));
            asm volatile("cp.async.cg.shared.global [%0], [%1], 16, 16;"
                         :: "r"(d), "l"(s));
        }
        asm volatile("cp.async.commit_group;");
    };

    issue(0);
    issue(1);
    for (int kc = 0; kc < nk; kc++) {
        if (kc + 2 < nk) {
            issue(kc + 2);
            asm volatile("cp.async.wait_group 2;");
        } else if (kc + 1 < nk) {
            asm volatile("cp.async.wait_group 1;");
        } else {
            asm volatile("cp.async.wait_group 0;");
        }
        __syncthreads();
        const bf16* As = sm + (kc % 3) * CST;
        const bf16* Bs = As + CA_ST;
        #pragma unroll
        for (int ks = 0; ks < 4; ks++) {
            int c0 = ks * 2;
            uint32_t a[2][4];
            #pragma unroll
            for (int mt = 0; mt < 2; mt++)
                ldsm4(a[mt], As + (wm + mt * 16 + ra) * 64 + (((c0 + ca) ^ fsw) * 8));
            uint32_t q[2][4];
            #pragma unroll
            for (int ntp = 0; ntp < 2; ntp++)
                ldsm4(q[ntp], Bs + (wn + ntp * 16 + nboff) * 64 + (((c0 + cb) ^ fsw) * 8));
            #pragma unroll
            for (int ntp = 0; ntp < 2; ntp++)
                #pragma unroll
                for (int h = 0; h < 2; h++)
                    #pragma unroll
                    for (int mt = 0; mt < 2; mt++)
                        mma16(acc[mt][ntp * 2 + h], a[mt], q[ntp][h * 2], q[ntp][h * 2 + 1]);
        }
        __syncthreads();
    }

    #pragma unroll
    for (int mt = 0; mt < 2; mt++) {
        int r0 = m0 + wm + mt * 16 + g;
        #pragma unroll
        for (int nt = 0; nt < 4; nt++) {
            int cc = n0 + wn + nt * 8 + tg * 2;
            float bx = bias ? bias[cc] : 0.f;
            float by = bias ? bias[cc + 1] : 0.f;
            float v0 = acc[mt][nt][0] + bx, v1 = acc[mt][nt][1] + by;
            float v2 = acc[mt][nt][2] + bx, v3 = acc[mt][nt][3] + by;
            if (doRelu) {
                v0 = fmaxf(v0, 0.f); v1 = fmaxf(v1, 0.f);
                v2 = fmaxf(v2, 0.f); v3 = fmaxf(v3, 0.f);
            }
            if (r0 < M)     *(bf162*)(C + (size_t)r0 * ldc + cc)       = __floats2bfloat162_rn(v0, v1);
            if (r0 + 8 < M) *(bf162*)(C + (size_t)(r0 + 8) * ldc + cc) = __floats2bfloat162_rn(v2, v3);
        }
    }
}

// ============ GEMM B: 128x256 tile, 512 thr, 2-stage (proven) =============
//  requires: K % 64 == 0, N % 256 == 0; dyn smem 98304 B
#define A_ST (128 * KC)
#define B_ST (256 * KC)
#define ST (A_ST + B_ST)
__global__ __launch_bounds__(512) void k_gemmB(
    const bf16* __restrict__ A, int lda,
    const bf16* __restrict__ W, int ldw,
    const float* __restrict__ bias,
    bf16* __restrict__ C, int ldc,
    int M, int N, int K, int doRelu)
{
    extern __shared__ bf16 sm[];
    const int tid = threadIdx.x;
    const int warp = tid >> 5, lane = tid & 31;
    const int m0 = blockIdx.y * 128, n0 = blockIdx.x * 256;
    const int wm = (warp >> 2) * 32;
    const int wn = (warp & 3) * 64;
    const int g = lane >> 2, tg = lane & 3;

    float acc[2][8][4];
    #pragma unroll
    for (int i = 0; i < 2; i++)
        #pragma unroll
        for (int j = 0; j < 8; j++)
            #pragma unroll
            for (int c = 0; c < 4; c++) acc[i][j][c] = 0.f;

    const int arow = tid >> 2;
    const int ac0 = (tid & 3) * 2;
    const int asw = arow & 7;
    const int brow = tid >> 1;
    const int bc0 = (tid & 1) * 4;
    const int bsw = brow & 7;

    const int garow = m0 + arow;
    const bool aok = garow < M;
    const int arc = aok ? garow : 0;

    const int ra = (lane & 7) + (lane & 8);
    const int ca = (lane >> 4) & 1;
    const int nboff = (lane & 7) + ((lane >> 4) & 1) * 8;
    const int cb = (lane >> 3) & 1;
    const int fsw = lane & 7;

    const int nk = K / KC;

    auto issue = [&](int kc) {
        int k0 = kc * KC;
        bf16* As = sm + (kc & 1) * ST;
        bf16* Bs = As + A_ST;
        #pragma unroll
        for (int j = 0; j < 2; j++) {
            int c = ac0 + j;
            const bf16* s = A + (size_t)arc * lda + k0 + c * 8;
            uint32_t d = (uint32_t)__cvta_generic_to_shared(As + arow * 64 + ((c ^ asw) * 8));
            int sz = aok ? 16 : 0;
            asm volatile("cp.async.cg.shared.global [%0], [%1], 16, %2;"
                         :: "r"(d), "l"(s), "r"(sz));
        }
        #pragma unroll
        for (int j = 0; j < 4; j++) {
            int c = bc0 + j;
            const bf16* s = W + (size_t)(n0 + brow) * ldw + k0 + c * 8;
            uint32_t d = (uint32_t)__cvta_generic_to_shared(Bs + brow * 64 + ((c ^ bsw) * 8));
            asm volatile("cp.async.cg.shared.global [%0], [%1], 16, 16;"
                         :: "r"(d), "l"(s));
        }
        asm volatile("cp.async.commit_group;");
    };

    issue(0);
    for (int kc = 0; kc < nk; kc++) {
        if (kc + 1 < nk) {
            issue(kc + 1);
            asm volatile("cp.async.wait_group 1;");
        } else {
            asm volatile("cp.async.wait_group 0;");
        }
        __syncthreads();
        const bf16* As = sm + (kc & 1) * ST;
        const bf16* Bs = As + A_ST;
        #pragma unroll
        for (int ks = 0; ks < 4; ks++) {
            int c0 = ks * 2;
            uint32_t a[2][4];
            #pragma unroll
            for (int mt = 0; mt < 2; mt++)
                ldsm4(a[mt], As + (wm + mt * 16 + ra) * 64 + (((c0 + ca) ^ fsw) * 8));
            uint32_t q[4][4];
            #pragma unroll
            for (int ntp = 0; ntp < 4; ntp++)
                ldsm4(q[ntp], Bs + (wn + ntp * 16 + nboff) * 64 + (((c0 + cb) ^ fsw) * 8));
            #pragma unroll
            for (int ntp = 0; ntp < 4; ntp++)
                #pragma unroll
                for (int h = 0; h < 2; h++)
                    #pragma unroll
                    for (int mt = 0; mt < 2; mt++)
                        mma16(acc[mt][ntp * 2 + h], a[mt], q[ntp][h * 2], q[ntp][h * 2 + 1]);
        }
        __syncthreads();
    }

    #pragma unroll
    for (int mt = 0; mt < 2; mt++) {
        int r0 = m0 + wm + mt * 16 + g;
        #pragma unroll
        for (int nt = 0; nt < 8; nt++) {
            int cc = n0 + wn + nt * 8 + tg * 2;
            float bx = bias ? bias[cc] : 0.f;
            float by = bias ? bias[cc + 1] : 0.f;
            float v0 = acc[mt][nt][0] + bx, v1 = acc[mt][nt][1] + by;
            float v2 = acc[mt][nt][2] + bx, v3 = acc[mt][nt][3] + by;
            if (doRelu) {
                v0 = fmaxf(v0, 0.f); v1 = fmaxf(v1, 0.f);
                v2 = fmaxf(v2, 0.f); v3 = fmaxf(v3, 0.f);
            }
            if (r0 < M)     *(bf162*)(C + (size_t)r0 * ldc + cc)       = __floats2bfloat162_rn(v0, v1);
            if (r0 + 8 < M) *(bf162*)(C + (size_t)(r0 + 8) * ldc + cc) = __floats2bfloat162_rn(v2, v3);
        }
    }
}

// ---------------- per-combo combine (warp-per-row, bf16 IO) ----------------
__global__ __launch_bounds__(256) void k_comb_inside(int L, int ns, int M,
                                                     const float* __restrict__ b1) {
    int w = threadIdx.x >> 5, lane = threadIdx.x & 31;
    int rid = blockIdx.x * 8 + w;
    if (rid >= M) return;
    int batch = rid % BB;
    int t = rid / BB;
    int si = t % ns, b = t / ns;
    int s = si + 1;
    int il = offL(s) + b;
    int ir = offL(L - s) + b + s;
    const uint4* pl = (const uint4*)(g_P + ((size_t)il * BB + batch) * 3 * DD);
    const uint4* pr = (const uint4*)(g_P + ((size_t)ir * BB + batch) * 3 * DD);
    const uint4* xl = (const uint4*)(g_iv + ((size_t)il * BB + batch) * DD);
    const float4* b14 = (const float4*)b1;
    uint4* hrow = (uint4*)(g_Hb + (size_t)rid * DD);
    float dot = 0.f;
    #pragma unroll
    for (int i = 0; i < 3; i++) {
        int e = lane + 32 * i;
        uint4 a4 = pl[e];
        uint4 b4 = pr[DD / 8 + e];
        uint4 r4 = pr[2 * (DD / 8) + e];
        uint4 x4 = xl[e];
        float4 v0 = b14[2 * e], v1 = b14[2 * e + 1];
        float2 a0 = bf2f(a4.x), a1 = bf2f(a4.y), a2 = bf2f(a4.z), a3 = bf2f(a4.w);
        float2 c0 = bf2f(b4.x), c1 = bf2f(b4.y), c2 = bf2f(b4.z), c3 = bf2f(b4.w);
        float2 r0 = bf2f(r4.x), r1 = bf2f(r4.y), r2 = bf2f(r4.z), r3 = bf2f(r4.w);
        float2 x0 = bf2f(x4.x), x1 = bf2f(x4.y), x2 = bf2f(x4.z), x3 = bf2f(x4.w);
        uint4 o;
        *(bf162*)&o.x = __floats2bfloat162_rn(fmaxf(a0.x + c0.x + v0.x, 0.f), fmaxf(a0.y + c0.y + v0.y, 0.f));
        *(bf162*)&o.y = __floats2bfloat162_rn(fmaxf(a1.x + c1.x + v0.z, 0.f), fmaxf(a1.y + c1.y + v0.w, 0.f));
        *(bf162*)&o.z = __floats2bfloat162_rn(fmaxf(a2.x + c2.x + v1.x, 0.f), fmaxf(a2.y + c2.y + v1.y, 0.f));
        *(bf162*)&o.w = __floats2bfloat162_rn(fmaxf(a3.x + c3.x + v1.z, 0.f), fmaxf(a3.y + c3.y + v1.w, 0.f));
        hrow[e] = o;
        dot += x0.x * r0.x + x0.y * r0.y + x1.x * r1.x + x1.y * r1.y
             + x2.x * r2.x + x2.y * r2.y + x3.x * r3.x + x3.y * r3.y;
    }
    #pragma unroll
    for (int o = 16; o; o >>= 1) dot += __shfl_down_sync(0xffffffffu, dot, o);
    if (lane == 0)
        g_S[rid] = dot + g_isc[il * BB + batch] + g_isc[ir * BB + batch];
}

__global__ __launch_bounds__(256) void k_comb_outside(int L, int nso, int M,
                                                      const float* __restrict__ b1) {
    int w = threadIdx.x >> 5, lane = threadIdx.x & 31;
    int rid = blockIdx.x * 8 + w;
    if (rid >= M) return;
    int batch = rid % BB;
    int t = rid / BB;
    int k = t % nso, b = t / nso;
    int ip, isx;
    if (k < b) {
        int c = k;
        ip  = offL(b + L - c) + c;
        isx = offL(b - c) + c;
    } else {
        int c = b + L + 1 + (k - b);
        ip  = offL(c - b) + b;
        isx = offL(c - b - L) + b + L;
    }
    const uint4* pl = (const uint4*)(g_Po + ((size_t)ip * BB + batch) * DD);
    const uint4* pr = (const uint4*)(g_P + ((size_t)isx * BB + batch) * 3 * DD);
    const uint4* xp = (const uint4*)(g_ov + ((size_t)ip * BB + batch) * DD);
    const float4* b14 = (const float4*)b1;
    uint4* hrow = (uint4*)(g_Hb + (size_t)rid * DD);
    float dot = 0.f;
    #pragma unroll
    for (int i = 0; i < 3; i++) {
        int e = lane + 32 * i;
        uint4 a4 = pl[e];
        uint4 b4 = pr[DD / 8 + e];
        uint4 r4 = pr[2 * (DD / 8) + e];
        uint4 x4 = xp[e];
        float4 v0 = b14[2 * e], v1 = b14[2 * e + 1];
        float2 a0 = bf2f(a4.x), a1 = bf2f(a4.y), a2 = bf2f(a4.z), a3 = bf2f(a4.w);
        float2 c0 = bf2f(b4.x), c1 = bf2f(b4.y), c2 = bf2f(b4.z), c3 = bf2f(b4.w);
        float2 r0 = bf2f(r4.x), r1 = bf2f(r4.y), r2 = bf2f(r4.z), r3 = bf2f(r4.w);
        float2 x0 = bf2f(x4.x), x1 = bf2f(x4.y), x2 = bf2f(x4.z), x3 = bf2f(x4.w);
        uint4 o;
        *(bf162*)&o.x = __floats2bfloat162_rn(fmaxf(a0.x + c0.x + v0.x, 0.f), fmaxf(a0.y + c0.y + v0.y, 0.f));
        *(bf162*)&o.y = __floats2bfloat162_rn(fmaxf(a1.x + c1.x + v0.z, 0.f), fmaxf(a1.y + c1.y + v0.w, 0.f));
        *(bf162*)&o.z = __floats2bfloat162_rn(fmaxf(a2.x + c2.x + v1.x, 0.f), fmaxf(a2.y + c2.y + v1.y, 0.f));
        *(bf162*)&o.w = __floats2bfloat162_rn(fmaxf(a3.x + c3.x + v1.z, 0.f), fmaxf(a3.y + c3.y + v1.w, 0.f));
        hrow[e] = o;
        dot += x0.x * r0.x + x0.y * r0.y + x1.x * r1.x + x1.y * r1.y
             + x2.x * r2.x + x2.y * r2.y + x3.x * r3.x + x3.y * r3.y;
    }
    #pragma unroll
    for (int o = 16; o; o >>= 1) dot += __shfl_down_sync(0xffffffffu, dot, o);
    if (lane == 0)
        g_S[rid] = dot + g_osc[ip * BB + batch] + g_isc[isx * BB + batch];
}

// ---------------- softmax over splits + weighted mix into chart cell ------
__global__ __launch_bounds__(256) void k_smx(int ns, int cell0,
                                             const bf16* __restrict__ V,
                                             bf16* __restrict__ vout,
                                             float* __restrict__ scout) {
    int bid = blockIdx.x;
    int batch = bid % BB;
    int b = bid / BB;
    __shared__ float sv[40], wv[40];
    int base = (b * ns) * BB + batch;
    if (threadIdx.x < ns) sv[threadIdx.x] = g_S[base + threadIdx.x * BB];
    __syncthreads();
    if (threadIdx.x == 0) {
        float mx = -1e30f;
        for (int s = 0; s < ns; s++) mx = fmaxf(mx, sv[s]);
        float Z = 0.f;
        for (int s = 0; s < ns; s++) { float e = expf(sv[s] - mx); wv[s] = e; Z += e; }
        float inv = 1.f / Z, sc = 0.f;
        for (int s = 0; s < ns; s++) { wv[s] *= inv; sc += wv[s] * sv[s]; }
        scout[(cell0 + b) * BB + batch] = sc;
    }
    __syncthreads();
    bf16* orow = vout + ((size_t)(cell0 + b) * BB + batch) * DD;
    for (int d = threadIdx.x; d < DD; d += 256) {
        float acc = 0.f;
        for (int s = 0; s < ns; s++)
            acc += wv[s] * __bfloat162float(V[(size_t)(base + s * BB) * DD + d]);
        orow[d] = __float2bfloat16(acc);
    }
}

// ---------------- final cosine loss ----------------
__global__ __launch_bounds__(256) void k_loss(const float* __restrict__ base,
                                              float* __restrict__ out) {
    int bid = blockIdx.x;
    int batch = bid % BB;
    int n = bid / BB;
    const bf16* tv = g_ov + ((size_t)n * BB + batch) * DD;
    const float* bv = base + ((size_t)n * BB + batch) * DD;
    float dp = 0.f, n1 = 0.f, n2 = 0.f;
    for (int d = threadIdx.x; d < DD; d += 256) {
        float a = __bfloat162float(tv[d]), c = bv[d];
        dp += a * c; n1 += a * a; n2 += c * c;
    }
    dp = blockReduce256(dp);
    n1 = blockReduce256(n1);
    n2 = blockReduce256(n2);
    if (threadIdx.x == 0) {
        float den = fmaxf(sqrtf(n1) * sqrtf(n2), 1e-8f);
        atomicAdd(out, (1.f - dp / den) * (1.f / (NN * BB)));
    }
}

// ---------------- host launcher ----------------
static inline void launch_gemm(const bf16* A, int lda, const bf16* W, int ldw,
                               const float* bias, bf16* C, int ldc,
                               int M, int N, int K, int doRelu) {
    if (M >= 4096) {
        k_gemmB<<<dim3(N / 256, (M + 127) / 128), 512, 98304>>>(
            A, lda, W, ldw, bias, C, ldc, M, N, K, doRelu);
    } else {
        k_gemmC<<<dim3(N / 128, (M + 63) / 64), 256, 73728>>>(
            A, lda, W, ldw, bias, C, ldc, M, N, K, doRelu);
    }
}

extern "C" void kernel_launch(void* const* d_in, const int* in_sizes, int n_in,
                              void* d_out, int out_size) {
    const float* base = (const float*)d_in[0];
    const float* Wbil = (const float*)d_in[1];
    const float* W1   = (const float*)d_in[2];
    const float* b1   = (const float*)d_in[3];
    const float* W2   = (const float*)d_in[4];
    const float* b2   = (const float*)d_in[5];
    const float* rootb= (const float*)d_in[6];
    float* out = (float*)d_out;

    cudaFuncSetAttribute(k_gemmC, cudaFuncAttributeMaxDynamicSharedMemorySize, 73728);
    cudaFuncSetAttribute(k_gemmB, cudaFuncAttributeMaxDynamicSharedMemorySize, 98304);

    bf16 *p_iv, *p_ov, *p_P, *p_Po, *p_V, *p_Hb, *p_Wcatb, *p_W2b;
    float *p_isc, *p_osc;
    cudaGetSymbolAddress((void**)&p_iv,  g_iv);
    cudaGetSymbolAddress((void**)&p_ov,  g_ov);
    cudaGetSymbolAddress((void**)&p_P,   g_P);
    cudaGetSymbolAddress((void**)&p_Po,  g_Po);
    cudaGetSymbolAddress((void**)&p_Hb,  g_Hb);
    cudaGetSymbolAddress((void**)&p_V,   g_V);
    cudaGetSymbolAddress((void**)&p_Wcatb, g_Wcatb);
    cudaGetSymbolAddress((void**)&p_W2b,   g_W2b);
    cudaGetSymbolAddress((void**)&p_isc, g_isc);
    cudaGetSymbolAddress((void**)&p_osc, g_osc);

    k_init<<<(INIT_TOT + 255) / 256, 256>>>(base, rootb, W1, Wbil, W2, out);

    // projections for base cells (M = 1280)
    launch_gemm(p_iv, DD, p_Wcatb, DD, nullptr, p_P, 3 * DD, NN * BB, 3 * DD, DD, 0);

    // ---------------- inside pass ----------------
    for (int L = 2; L <= NN; L++) {
        int nb = NN + 1 - L, ns = L - 1;
        int M = nb * ns * BB;
        k_comb_inside<<<(M + 7) / 8, 256>>>(L, ns, M, b1);
        launch_gemm(p_Hb, DD, p_W2b, DD, b2, p_V, DD, M, DD, DD, 1);
        k_smx<<<nb * BB, 256>>>(ns, offL(L), p_V, p_iv, p_isc);
        if (L < NN) {
            size_t c0 = (size_t)offL(L);
            launch_gemm(p_iv + c0 * BB * DD, DD, p_Wcatb, DD, nullptr,
                        p_P + c0 * BB * 3 * DD, 3 * DD, nb * BB, 3 * DD, DD, 0);
        }
    }

    // root outside projection Po = ov_root @ W1a^T
    {
        size_t c0 = (size_t)offL(NN);
        launch_gemm(p_ov + c0 * BB * DD, DD, p_Wcatb, DD, nullptr,
                    p_Po + c0 * BB * DD, DD, BB, DD, DD, 0);
    }

    // ---------------- outside pass ----------------
    for (int L = NN - 1; L >= 1; L--) {
        int nb = NN + 1 - L, nso = NN - L;
        int M = nb * nso * BB;
        k_comb_outside<<<(M + 7) / 8, 256>>>(L, nso, M, b1);
        launch_gemm(p_Hb, DD, p_W2b, DD, b2, p_V, DD, M, DD, DD, 1);
        k_smx<<<nb * BB, 256>>>(nso, offL(L), p_V, p_ov, p_osc);
        if (L > 1) {
            size_t c0 = (size_t)offL(L);
            launch_gemm(p_ov + c0 * BB * DD, DD, p_Wcatb, DD, nullptr,
                        p_Po + c0 * BB * DD, DD, nb * BB, DD, DD, 0);
        }
    }

    k_loss<<<NN * BB, 256>>>(base, out);
}